// round 1
// baseline (speedup 1.0000x reference)
#include <cuda_runtime.h>
#include <math.h>
#include <stdint.h>

#define Bn 16
#define NC 80
#define Hn 128
#define Wn 128
#define MAXO 100
#define HWc (Hn*Wn)

struct __align__(16) Obj {
    float x1, y1, x2, y2;        // sorted target box (input coords)
    float cx, cy, wr, hr;        // center (feature coords), radii (as float)
    float i2sx2, i2sy2;          // 1/(2*s^2)
    float inv_gsum;              // 1/max(sum g, 1e-12)
    int   cls;
    int   valid;
    float pad0, pad1, pad2;
};

__device__ Obj    g_obj[Bn][MAXO];
__device__ double g_acc[4];   // 0: neg_loss, 1: pos_loss, 2: giou_sum, 3: w_sum
__device__ int    g_npos;

// ---------------------------------------------------------------------------
// Kernel 1: per-batch object sort (stable, descending area) + params + gsum
// ---------------------------------------------------------------------------
__global__ void prep_kernel(const float* __restrict__ ann) {
    int b = blockIdx.x;
    int tid = threadIdx.x;
    __shared__ float a[MAXO][5];
    __shared__ float key[MAXO];
    __shared__ int   sortedOf[MAXO];

    if (b == 0 && tid == 0) {
        g_acc[0] = 0.0; g_acc[1] = 0.0; g_acc[2] = 0.0; g_acc[3] = 0.0;
        g_npos = 0;
    }

    for (int i = tid; i < MAXO * 5; i += blockDim.x)
        a[i / 5][i % 5] = ann[(size_t)b * MAXO * 5 + i];
    __syncthreads();

    if (tid < MAXO) {
        float cls = a[tid][4];
        bool valid = cls >= 0.0f;
        float area = (a[tid][3] - a[tid][1] + 1.0f) * (a[tid][2] - a[tid][0] + 1.0f);
        key[tid] = valid ? area : -3.4e38f;
    }
    __syncthreads();

    if (tid < MAXO) {
        float ki = key[tid];
        int r = 0;
        #pragma unroll 4
        for (int j = 0; j < MAXO; j++) {
            float kj = key[j];
            if (kj > ki || (kj == ki && j < tid)) r++;
        }
        sortedOf[r] = tid;   // descending by key, stable
    }
    __syncthreads();

    if (tid < MAXO) {
        int i = sortedOf[tid];
        float x1 = a[i][0], y1 = a[i][1], x2 = a[i][2], y2 = a[i][3], cls = a[i][4];
        int valid = (cls >= 0.0f) ? 1 : 0;

        Obj o;
        o.x1 = x1; o.y1 = y1; o.x2 = x2; o.y2 = y2;
        o.cx = truncf((x1 + x2) * 0.5f / 4.0f);
        o.cy = truncf((y1 + y2) * 0.5f / 4.0f);
        float fx1 = fminf(fmaxf(x1 / 4.0f, 0.0f), (float)(Wn - 1));
        float fx2 = fminf(fmaxf(x2 / 4.0f, 0.0f), (float)(Wn - 1));
        float fy1 = fminf(fmaxf(y1 / 4.0f, 0.0f), (float)(Hn - 1));
        float fy2 = fminf(fmaxf(y2 / 4.0f, 0.0f), (float)(Hn - 1));
        int hr = (int)((fy2 - fy1) * 0.5f * 0.54f);
        int wr = (int)((fx2 - fx1) * 0.5f * 0.54f);
        float sx = (float)(2 * wr + 1) / 6.0f;
        float sy = (float)(2 * hr + 1) / 6.0f;
        o.wr = (float)wr; o.hr = (float)hr;
        o.i2sx2 = 1.0f / (2.0f * sx * sx);
        o.i2sy2 = 1.0f / (2.0f * sy * sy);

        // analytic gsum: separable window sums, clipped to image bounds
        int icx = (int)o.cx, icy = (int)o.cy;
        float sumx = 0.0f;
        int xa = max(0, icx - wr), xb = min(Wn - 1, icx + wr);
        for (int xx = xa; xx <= xb; xx++) {
            float dx = (float)xx - o.cx;
            sumx += __expf(-(dx * dx) * o.i2sx2);
        }
        float sumy = 0.0f;
        int ya = max(0, icy - hr), yb = min(Hn - 1, icy + hr);
        for (int yy = ya; yy <= yb; yy++) {
            float dy = (float)yy - o.cy;
            sumy += __expf(-(dy * dy) * o.i2sy2);
        }
        float gs = fmaxf(sumx * sumy, 1e-12f);
        o.inv_gsum = valid ? (1.0f / gs) : 0.0f;

        int ic = (int)cls;
        if (ic < 0) ic = 0;
        if (ic > NC - 1) ic = NC - 1;
        o.cls = ic;
        o.valid = valid;
        o.pad0 = o.pad1 = o.pad2 = 0.0f;

        g_obj[b][tid] = o;
    }
}

// ---------------------------------------------------------------------------
// Kernel 2: fused focal (base + sparse corrections) + GIoU. One row per block.
// ---------------------------------------------------------------------------
__global__ void __launch_bounds__(128) main_kernel(const float* __restrict__ hm,
                                                   const float* __restrict__ wh) {
    int b = blockIdx.x >> 7;
    int y = blockIdx.x & 127;
    int x = threadIdx.x;

    __shared__ Obj sh[MAXO];
    {
        const float4* src = (const float4*)&g_obj[b][0];
        float4* dst = (float4*)&sh[0];
        for (int i = threadIdx.x; i < MAXO * 4; i += blockDim.x) dst[i] = src[i];
    }
    __syncthreads();

    float fx = (float)x, fy = (float)y;

    // ---- covering-object scan (objects sorted area-desc; invalid are last) ----
    float covG[MAXO];
    int   covCls[MAXO];
    int count = 0;
    int owner = -1;
    float gOwner = 0.0f;
    for (int n = 0; n < MAXO; n++) {
        if (!sh[n].valid) break;   // sorted: invalid objects are all at the tail
        float dx = fx - sh[n].cx;
        float dy = fy - sh[n].cy;
        if (fabsf(dx) <= sh[n].wr && fabsf(dy) <= sh[n].hr) {
            float g = __expf(-(dx * dx) * sh[n].i2sx2) * __expf(-(dy * dy) * sh[n].i2sy2);
            covG[count] = g;
            covCls[count] = sh[n].cls;
            count++;
            owner = n;       // owner = largest sorted index with g>0
            gOwner = g;
        }
    }

    // ---- focal base: tgt = 0 form for all classes ----
    const float* hp = hm + ((size_t)b * NC) * HWc + (size_t)y * Wn + x;
    float accNeg = 0.0f;
    #pragma unroll 4
    for (int c = 0; c < NC; c++) {
        float logit = hp[(size_t)c * HWc];
        float e = __expf(logit);
        float s = e / (1.0f + e);                 // sigmoid
        accNeg += __logf(1.0f + e) * s * s;       // -log(1-s)*s^2
    }

    // ---- sparse corrections for covered pixel-classes ----
    float accPos = 0.0f;
    int npos = 0;
    for (int i = 0; i < count; i++) {
        float gi = covG[i];
        int ci = covCls[i];
        bool isMax = true;
        for (int j = 0; j < count; j++) {
            if (j == i) continue;
            if (covCls[j] == ci && (covG[j] > gi || (covG[j] == gi && j < i))) {
                isMax = false;
                break;
            }
        }
        if (!isMax) continue;
        // tgt for class ci at this pixel is gi
        float logit = hp[(size_t)ci * HWc];
        float e = __expf(logit);
        float s = e / (1.0f + e);
        float base = __logf(1.0f + e) * s * s;
        if (gi == 1.0f) {
            float oms = 1.0f / (1.0f + e);        // 1 - s
            accPos += -__logf(s) * oms * oms;     // pos focal term
            accNeg -= base;                       // remove neg base (neg mask = 0)
            npos++;
        } else {
            float nt = 1.0f - gi;
            float nt2 = nt * nt;
            accNeg += base * (nt2 * nt2 - 1.0f);  // scale base by (1-tgt)^4
        }
    }

    // ---- GIoU on the owned pixel ----
    float accG = 0.0f, accWs = 0.0f;
    if (owner >= 0) {
        Obj o = sh[owner];
        float w = gOwner * o.inv_gsum;
        size_t wb = (size_t)b * 4 * HWc + (size_t)y * Wn + x;
        float wh0 = wh[wb];
        float wh1 = wh[wb + HWc];
        float wh2 = wh[wb + 2 * (size_t)HWc];
        float wh3 = wh[wb + 3 * (size_t)HWc];
        float bx = fx * 4.0f, by = fy * 4.0f;
        float p0 = bx - wh0, p1 = by - wh1, p2 = bx + wh2, p3 = by + wh3;
        float t0 = o.x1, t1 = o.y1, t2 = o.x2, t3 = o.y2;
        float ltx = fmaxf(p0, t0), lty = fmaxf(p1, t1);
        float rbx = fminf(p2, t2), rby = fminf(p3, t3);
        float iw = fmaxf(rbx - ltx + 1.0f, 0.0f);
        float ih = fmaxf(rby - lty + 1.0f, 0.0f);
        float ov = iw * ih;
        float ap = (p2 - p0 + 1.0f) * (p3 - p1 + 1.0f);
        float ag = (t2 - t0 + 1.0f) * (t3 - t1 + 1.0f);
        float u = ap + ag - ov;
        float iou = ov / u;
        float e1x = fminf(p0, t0), e1y = fminf(p1, t1);
        float e2x = fmaxf(p2, t2), e2y = fmaxf(p3, t3);
        float ew = fmaxf(e2x - e1x + 1.0f, 0.0f);
        float eh = fmaxf(e2y - e1y + 1.0f, 0.0f);
        float ea = ew * eh;
        float giou = iou - (ea - u) / ea;
        accG = (1.0f - giou) * w;
        accWs = w;
    }

    // ---- reductions: warp shuffle -> shared -> one double atomic per block ----
    #pragma unroll
    for (int off = 16; off > 0; off >>= 1) {
        accNeg += __shfl_down_sync(0xffffffffu, accNeg, off);
        accPos += __shfl_down_sync(0xffffffffu, accPos, off);
        accG   += __shfl_down_sync(0xffffffffu, accG,   off);
        accWs  += __shfl_down_sync(0xffffffffu, accWs,  off);
        npos   += __shfl_down_sync(0xffffffffu, npos,   off);
    }
    __shared__ float rNeg[4], rPos[4], rG[4], rW[4];
    __shared__ int rN[4];
    int wid = threadIdx.x >> 5, lane = threadIdx.x & 31;
    if (lane == 0) { rNeg[wid] = accNeg; rPos[wid] = accPos; rG[wid] = accG; rW[wid] = accWs; rN[wid] = npos; }
    __syncthreads();
    if (threadIdx.x == 0) {
        float sn = 0.f, sp = 0.f, sg = 0.f, sw = 0.f;
        int np = 0;
        #pragma unroll
        for (int i = 0; i < 4; i++) { sn += rNeg[i]; sp += rPos[i]; sg += rG[i]; sw += rW[i]; np += rN[i]; }
        atomicAdd(&g_acc[0], (double)sn);
        atomicAdd(&g_acc[1], (double)sp);
        atomicAdd(&g_acc[2], (double)sg);
        atomicAdd(&g_acc[3], (double)sw);
        atomicAdd(&g_npos, np);
    }
}

// ---------------------------------------------------------------------------
// Kernel 3: finalize
// ---------------------------------------------------------------------------
__global__ void fin_kernel(float* out, int out_size) {
    double neg = g_acc[0], pos = g_acc[1], gi = g_acc[2], ws = g_acc[3];
    int np = g_npos;
    double hm_loss = (np > 0) ? ((pos + neg) / (double)np) : neg;   // * HM_W (1.0)
    double wh_loss = gi / (ws + 1e-4) * 0.1;                        // * WH_W
    if (out_size >= 1) out[0] = (float)hm_loss;
    if (out_size >= 2) out[1] = (float)wh_loss;
}

// ---------------------------------------------------------------------------
extern "C" void kernel_launch(void* const* d_in, const int* in_sizes, int n_in,
                              void* d_out, int out_size) {
    const float* hm  = (const float*)d_in[0];   // (16, 80, 128, 128)
    const float* wh  = (const float*)d_in[1];   // (16, 4, 128, 128)
    const float* ann = (const float*)d_in[2];   // (16, 100, 5)
    float* out = (float*)d_out;

    prep_kernel<<<Bn, 128>>>(ann);
    main_kernel<<<Bn * Hn, 128>>>(hm, wh);
    fin_kernel<<<1, 1>>>(out, out_size);
}